// round 13
// baseline (speedup 1.0000x reference)
#include <cuda_runtime.h>
#include <cuda_fp16.h>
#include <math.h>
#include <stdint.h>

#define BB 2
#define LL 4096
#define CC 1024
#define NHH 16
#define DHH 64
#define NR 1638
#define QKVW 3072
#define GK 1024

// ------------------------- scratch (device globals; no runtime alloc) -------
__device__ float g_mean[BB * CC];
__device__ double g_part[BB * 8 * CC];
__device__ float g_mse[BB * LL];
__device__ int g_idx[BB * NR];
__device__ float g_bias[QKVW];
__device__ __half g_qkvh[(size_t)BB * NR * QKVW];  // (b, i, 3*C) fp16
// fp16 attention operands
__device__ __half g_qh[(size_t)BB * NHH * NR * DHH];
__device__ __half g_kh[(size_t)BB * NHH * NR * DHH];
__device__ __half g_vh[(size_t)BB * NR * CC];
// fp16 GEMM operands
__device__ __half g_ax[(size_t)BB * NR * GK];   // x[idx] fp16
__device__ __half g_wq[(size_t)QKVW * GK];      // Wqkv fp16
__device__ __half g_wp[(size_t)CC * GK];        // Wproj fp16
__device__ __half g_ao[(size_t)BB * NR * GK];   // attn out fp16 (written by fattn)

// ------------------------- helpers -----------------------------------------
__device__ __forceinline__ float warpSumF(float v) {
#pragma unroll
    for (int m = 16; m; m >>= 1) v += __shfl_xor_sync(0xffffffffu, v, m);
    return v;
}
__device__ __forceinline__ double warpSumD(double v) {
#pragma unroll
    for (int m = 16; m; m >>= 1) v += __shfl_xor_sync(0xffffffffu, v, m);
    return v;
}
__device__ __forceinline__ uint32_t s2u(const void* p) {
    uint32_t a;
    asm("{ .reg .u64 t; cvta.to.shared.u64 t, %1; cvt.u32.u64 %0, t; }" : "=r"(a) : "l"(p));
    return a;
}
__device__ __forceinline__ uint32_t packh(float a, float b) {
    __half2 t = __floats2half2_rn(a, b);
    return *(uint32_t*)&t;
}
#define LDSM4(d0, d1, d2, d3, addr) \
    asm volatile("ldmatrix.sync.aligned.m8n8.x4.shared.b16 {%0,%1,%2,%3}, [%4];" \
                 : "=r"(d0), "=r"(d1), "=r"(d2), "=r"(d3) : "r"(addr))
#define LDSM2(d0, d1, addr) \
    asm volatile("ldmatrix.sync.aligned.m8n8.x2.shared.b16 {%0,%1}, [%2];" \
                 : "=r"(d0), "=r"(d1) : "r"(addr))
#define LDSM2T(d0, d1, addr) \
    asm volatile("ldmatrix.sync.aligned.m8n8.x2.trans.shared.b16 {%0,%1}, [%2];" \
                 : "=r"(d0), "=r"(d1) : "r"(addr))
#define MMA16816(c0, c1, c2, c3, a0, a1, a2, a3, b0, b1) \
    asm volatile("mma.sync.aligned.m16n8k16.row.col.f32.f16.f16.f32 " \
                 "{%0,%1,%2,%3}, {%4,%5,%6,%7}, {%8,%9}, {%0,%1,%2,%3};" \
                 : "+f"(c0), "+f"(c1), "+f"(c2), "+f"(c3) \
                 : "r"(a0), "r"(a1), "r"(a2), "r"(a3), "r"(b0), "r"(b1))

// ------------------------- stage 1: mean over L (fp64 accum) ---------------
__global__ void k_colsum(const float* __restrict__ x) {
    int c = blockIdx.x * 256 + threadIdx.x;
    int b = blockIdx.z;
    int l0 = blockIdx.y * 512;
    const float* p = x + ((size_t)b * LL + l0) * CC + c;
    double a0 = 0, a1 = 0, a2 = 0, a3 = 0;
#pragma unroll 4
    for (int l = 0; l < 512; l += 4) {
        a0 += (double)p[(size_t)(l + 0) * CC];
        a1 += (double)p[(size_t)(l + 1) * CC];
        a2 += (double)p[(size_t)(l + 2) * CC];
        a3 += (double)p[(size_t)(l + 3) * CC];
    }
    g_part[(b * 8 + blockIdx.y) * CC + c] = a0 + a1 + a2 + a3;
}

__global__ void k_meanfin() {
    int i = blockIdx.x * 256 + threadIdx.x;
    int b = i >> 10, c = i & 1023;
    double s = 0;
#pragma unroll
    for (int k = 0; k < 8; k++) s += g_part[(b * 8 + k) * CC + c];
    g_mean[b * CC + c] = (float)(s * (1.0 / (double)LL));
}

// ------------------------- stage 2: per-row mse (fp64 accum) ---------------
__global__ void k_mse(const float* __restrict__ x) {
    int l = blockIdx.x, b = blockIdx.y;
    const float* xr = x + ((size_t)b * LL + l) * CC;
    double acc = 0;
#pragma unroll
    for (int k = 0; k < 4; k++) {
        int c = threadIdx.x + k * 256;
        double d = (double)xr[c] - (double)g_mean[b * CC + c];
        acc += d * d;
    }
    acc = warpSumD(acc);
    __shared__ double red[8];
    if ((threadIdx.x & 31) == 0) red[threadIdx.x >> 5] = acc;
    __syncthreads();
    if (threadIdx.x == 0) {
        double t = 0;
#pragma unroll
        for (int w = 0; w < 8; w++) t += red[w];
        g_mse[b * LL + l] = (float)t;
    }
}

// ------------------------- stage 3: top-NR radix select (parallel scan) ----
__global__ void k_topk() {
    __shared__ unsigned int hist[256];
    __shared__ unsigned int suf[256];
    __shared__ unsigned int sh_pref, sh_rank, sh_cgt, sh_ceq;
    int b = blockIdx.x, tid = threadIdx.x;
    unsigned int key[4];
#pragma unroll
    for (int k = 0; k < 4; k++)
        key[k] = __float_as_uint(g_mse[b * LL + tid * 4 + k]);
    if (tid == 0) { sh_pref = 0; sh_rank = NR; }
#pragma unroll
    for (int pass = 0; pass < 4; pass++) {
        int shift = 24 - pass * 8;
        if (tid < 256) hist[tid] = 0;
        __syncthreads();
        unsigned int pref = sh_pref, r = sh_rank;
        unsigned int himask = (pass == 0) ? 0u : (0xFFFFFFFFu << (shift + 8));
#pragma unroll
        for (int k = 0; k < 4; k++)
            if ((key[k] & himask) == pref)
                atomicAdd(&hist[(key[k] >> shift) & 255], 1u);
        __syncthreads();
        if (tid < 256) suf[tid] = hist[tid];
        __syncthreads();
#pragma unroll
        for (int off = 1; off < 256; off <<= 1) {
            unsigned int t = 0;
            if (tid < 256 && tid + off < 256) t = suf[tid + off];
            __syncthreads();
            if (tid < 256) suf[tid] += t;
            __syncthreads();
        }
        if (tid < 256) {
            unsigned int hi = (tid == 255) ? 0u : suf[tid + 1];
            if (suf[tid] >= r && hi < r) {
                sh_pref = pref | ((unsigned int)tid << shift);
                sh_rank = r - hi;
            }
        }
        __syncthreads();
    }
    if (tid == 0) { sh_cgt = 0; sh_ceq = 0; }
    __syncthreads();
    unsigned int thr = sh_pref, need = sh_rank;
    int ngt = NR - (int)need;
#pragma unroll
    for (int k = 0; k < 4; k++) {
        if (key[k] > thr) {
            unsigned int p = atomicAdd(&sh_cgt, 1u);
            g_idx[b * NR + p] = tid * 4 + k;
        } else if (key[k] == thr) {
            unsigned int p = atomicAdd(&sh_ceq, 1u);
            if (p < need) g_idx[b * NR + ngt + p] = tid * 4 + k;
        }
    }
}

// ------------------------- stage 4: fused bias ------------------------------
__global__ void k_bias(const float* __restrict__ qb, const float* __restrict__ vb) {
    int i = blockIdx.x * 256 + threadIdx.x;
    if (i < QKVW) g_bias[i] = (i < CC) ? qb[i] : ((i < 2 * CC) ? 0.f : vb[i - 2 * CC]);
}

// ------------------------- pack kernels (fp32 -> fp16) ----------------------
__global__ void k_packW(const float* __restrict__ W, __half* __restrict__ out, int total) {
    int i = (blockIdx.x * 256 + threadIdx.x) * 4;
    if (i >= total) return;
    float4 v = *(const float4*)(W + i);
    *(__half2*)(out + i) = __floats2half2_rn(v.x, v.y);
    *(__half2*)(out + i + 2) = __floats2half2_rn(v.z, v.w);
}
__global__ void k_packAx(const float* __restrict__ x, __half* __restrict__ out) {
    int i = (blockIdx.x * 256 + threadIdx.x) * 4;
    if (i >= BB * NR * CC) return;
    int c = i & 1023;
    int t = i >> 10;
    int r = t % NR, b = t / NR;
    int li = g_idx[b * NR + r];
    float4 v = *(const float4*)(x + ((size_t)b * LL + li) * CC + c);
    *(__half2*)(out + i) = __floats2half2_rn(v.x, v.y);
    *(__half2*)(out + i + 2) = __floats2half2_rn(v.z, v.w);
}

// ------------------------- tensor GEMM via mma.sync fp16 -------------------
// BM=64, BN=128, BK=32, 8 warps (2x4), warp tile 32x32.
// Loaders: 16 halves (2 x uint4) per thread per tile row-segment.
// MODE 0: C = A@B^T + bias -> fp16 Ch (batched by cBatch).
// MODE 1: out[(b,idx[r])] = x[(b,idx[r])] + A@B^T + bias  (fused proj+scatter)
#define PITCH 40
#define KITERS (GK / 32)   // 32

template <int MODE>
__global__ void __launch_bounds__(256, 2) k_mgemm(
    const __half* __restrict__ A, const __half* __restrict__ Bm,
    const float* __restrict__ bias,
    __half* __restrict__ Ch, float* __restrict__ outp, const float* __restrict__ xres,
    int M, int N, size_t aBatch, size_t cBatch)
{
    __shared__ __half Asm[2][64 * PITCH];
    __shared__ __half Bsm[2][128 * PITCH];

    int tid = threadIdx.x, wid = tid >> 5, lane = tid & 31;
    int bm = blockIdx.y * 64, bn = blockIdx.x * 128, b = blockIdx.z;
    int wm = wid >> 2, wn = wid & 3;             // 2 x 4 warp grid, tile 32x32
    const __half* Ab = A + (size_t)b * aBatch;

    // B loader: 256 threads -> 128 rows x 2 col-halves of 16 halves each
    int lr = tid >> 1, lc = (tid & 1) * 16;
    // A loader: first 128 threads -> 64 rows x 2 col-halves of 16 halves each
    int ar = tid >> 1;
    bool aok = (tid < 128) && (bm + ar < M);
    const uint4 z4 = make_uint4(0, 0, 0, 0);
    const __half* aRow = Ab + (size_t)(aok ? bm + ar : 0) * GK + lc;
    const __half* bRow = Bm + (size_t)(bn + lr) * GK + lc;

    uint32_t aL = s2u(&Asm[0][0]) +
                  ((wm * 32 + (lane & 15)) * PITCH + (lane >> 4) * 8) * 2;
    uint32_t bL = s2u(&Bsm[0][0]) +
                  ((wn * 32 + (lane & 7)) * PITCH + ((lane >> 3) & 1) * 8) * 2;
    const uint32_t BUFA = 64 * PITCH * 2, BUFB = 128 * PITCH * 2;

    float acc[2][4][4];
#pragma unroll
    for (int i = 0; i < 2; i++)
#pragma unroll
        for (int j = 0; j < 4; j++)
#pragma unroll
            for (int r = 0; r < 4; r++) acc[i][j][r] = 0.f;

    {   // prologue: stage kt=0 into buffer 0 (2 x uint4 = 16 halves each)
        const uint4* bg = (const uint4*)bRow;
        *(uint4*)(Bsm[0] + lr * PITCH + lc) = bg[0];
        *(uint4*)(Bsm[0] + lr * PITCH + lc + 8) = bg[1];
        if (tid < 128) {
            const uint4* ag = (const uint4*)aRow;
            *(uint4*)(Asm[0] + ar * PITCH + lc) = aok ? ag[0] : z4;
            *(uint4*)(Asm[0] + ar * PITCH + lc + 8) = aok ? ag[1] : z4;
        }
    }
    __syncthreads();

    for (int kt = 0; kt < KITERS; kt++) {
        int s = kt & 1;
        uint4 na0, na1, nb0, nb1;
        bool more = (kt + 1 < KITERS);
        if (more) {
            const uint4* bg = (const uint4*)(bRow + (kt + 1) * 32);
            nb0 = bg[0]; nb1 = bg[1];
            if (tid < 128) {
                const uint4* ag = (const uint4*)(aRow + (kt + 1) * 32);
                na0 = aok ? ag[0] : z4;
                na1 = aok ? ag[1] : z4;
            }
        }

        uint32_t aBase = aL + s * BUFA, bBase = bL + s * BUFB;
#pragma unroll
        for (int k16 = 0; k16 < 2; k16++) {
            uint32_t af[2][4], bf[4][2];
#pragma unroll
            for (int i = 0; i < 2; i++)
                LDSM4(af[i][0], af[i][1], af[i][2], af[i][3],
                      aBase + (i * 16 * PITCH + k16 * 16) * 2);
#pragma unroll
            for (int j = 0; j < 4; j++)
                LDSM2(bf[j][0], bf[j][1],
                      bBase + (j * 8 * PITCH + k16 * 16) * 2);
#pragma unroll
            for (int i = 0; i < 2; i++)
#pragma unroll
                for (int j = 0; j < 4; j++)
                    MMA16816(acc[i][j][0], acc[i][j][1], acc[i][j][2], acc[i][j][3],
                             af[i][0], af[i][1], af[i][2], af[i][3],
                             bf[j][0], bf[j][1]);
        }

        if (more) {
            int d = s ^ 1;
            *(uint4*)((char*)(Bsm[0] + lr * PITCH + lc) + d * BUFB) = nb0;
            *(uint4*)((char*)(Bsm[0] + lr * PITCH + lc + 8) + d * BUFB) = nb1;
            if (tid < 128) {
                *(uint4*)((char*)(Asm[0] + ar * PITCH + lc) + d * BUFA) = na0;
                *(uint4*)((char*)(Asm[0] + ar * PITCH + lc + 8) + d * BUFA) = na1;
            }
        }
        __syncthreads();
    }

    int rq = lane >> 2, cq = (lane & 3) * 2;
    if (MODE == 0) {
        __half* Cb = Ch + (size_t)b * cBatch;
#pragma unroll
        for (int i = 0; i < 2; i++) {
#pragma unroll
            for (int hh = 0; hh < 2; hh++) {
                int r = bm + wm * 32 + i * 16 + rq + hh * 8;
                if (r >= M) continue;
#pragma unroll
                for (int j = 0; j < 4; j++) {
                    int col = bn + wn * 32 + j * 8 + cq;
                    float a0 = acc[i][j][hh * 2 + 0] + bias[col];
                    float a1 = acc[i][j][hh * 2 + 1] + bias[col + 1];
                    *(__half2*)(Cb + (size_t)r * N + col) = __floats2half2_rn(a0, a1);
                }
            }
        }
    } else {
#pragma unroll
        for (int i = 0; i < 2; i++) {
#pragma unroll
            for (int hh = 0; hh < 2; hh++) {
                int r = bm + wm * 32 + i * 16 + rq + hh * 8;
                if (r >= M) continue;
                int li = g_idx[b * NR + r];
                size_t rowoff = ((size_t)b * LL + li) * CC;
#pragma unroll
                for (int j = 0; j < 4; j++) {
                    int col = bn + wn * 32 + j * 8 + cq;
                    float a0 = acc[i][j][hh * 2 + 0] + bias[col];
                    float a1 = acc[i][j][hh * 2 + 1] + bias[col + 1];
                    float2 xv = *(const float2*)(xres + rowoff + col);
                    *(float2*)(outp + rowoff + col) = make_float2(a0 + xv.x, a1 + xv.y);
                }
            }
        }
    }
}

// ------------------------- stage 5: l2norm + scale + rope (-> fp16) --------
__global__ void k_qkprep(const float* __restrict__ rope, const float* __restrict__ slog) {
    int i = blockIdx.x, b = blockIdx.y;
    int h = threadIdx.x >> 5, p = threadIdx.x & 31;
    int li = g_idx[b * NR + i];
    const __half* base = g_qkvh + ((size_t)b * NR + i) * QKVW;
    float2 q = __half22float2(*(const __half2*)(base + h * 64 + 2 * p));
    float2 kk = __half22float2(*(const __half2*)(base + CC + h * 64 + 2 * p));
    __half2 vh = *(const __half2*)(base + 2 * CC + h * 64 + 2 * p);
    float nq = warpSumF(q.x * q.x + q.y * q.y);
    float nk = warpSumF(kk.x * kk.x + kk.y * kk.y);
    float sm = __expf(fminf(slog[h], 4.6051701859880914f));
    float qs = sm / fmaxf(sqrtf(nq), 1e-12f);
    float ks = 1.f / fmaxf(sqrtf(nk), 1e-12f);
    float cv = rope[(size_t)li * 32 + p];
    float sv = rope[(size_t)LL * 32 + (size_t)li * 32 + p];
    float q0 = q.x * qs, q1 = q.y * qs;
    float k0 = kk.x * ks, k1 = kk.y * ks;
    size_t off = (((size_t)b * NHH + h) * NR + i) * DHH + 2 * p;
    *(__half2*)(g_qh + off) = __floats2half2_rn(cv * q0 - sv * q1, sv * q0 + cv * q1);
    *(__half2*)(g_kh + off) = __floats2half2_rn(cv * k0 - sv * k1, sv * k0 + cv * k1);
    *(__half2*)(g_vh + ((size_t)b * NR + i) * CC + h * 64 + 2 * p) = vh;
}

// ------------------------- stage 6: tensor-core flash attention ------------
#define FAP 72
#define NCHUNK 26
#define FA_SMEM ((128 * FAP + 4 * 64 * FAP) * 2)

__global__ void __launch_bounds__(256, 2) k_fattn() {
    extern __shared__ __half fsm[];
    __half* Qs = fsm;
    __half* Ks = Qs + 128 * FAP;
    __half* Vs = Ks + 2 * 64 * FAP;
    int tid = threadIdx.x, wid = tid >> 5, lane = tid & 31;
    int qbase = blockIdx.x * 128;
    int h = blockIdx.y, b = blockIdx.z;
    const __half* Qg = g_qh + ((size_t)(b * NHH + h)) * NR * DHH;
    const __half* Kg = g_kh + ((size_t)(b * NHH + h)) * NR * DHH;
    const __half* Vg = g_vh + (size_t)b * NR * CC + h * 64;

    const uint4 z4 = make_uint4(0, 0, 0, 0);
    int lrow = tid >> 1, lhalf = tid & 1;
    int krow = tid >> 2, kq = tid & 3;

    {   // Q tile
        int qi = qbase + lrow;
        const uint4* src = (const uint4*)(Qg + (size_t)(qi < NR ? qi : 0) * DHH + lhalf * 32);
        uint4* dst = (uint4*)&Qs[lrow * FAP + lhalf * 32];
#pragma unroll
        for (int t = 0; t < 4; t++) dst[t] = (qi < NR) ? src[t] : z4;
    }
    {   // K/V chunk 0
        const uint4* ks = (const uint4*)(Kg + (size_t)krow * DHH + kq * 16);
        const uint4* vs = (const uint4*)(Vg + (size_t)krow * CC + kq * 16);
        uint4* kd = (uint4*)&Ks[krow * FAP + kq * 16];
        uint4* vd = (uint4*)&Vs[krow * FAP + kq * 16];
        kd[0] = ks[0]; kd[1] = ks[1];
        vd[0] = vs[0]; vd[1] = vs[1];
    }
    __syncthreads();

    uint32_t qf[4][4];
    uint32_t qaddr = s2u(Qs) + ((wid * 16 + (lane & 15)) * FAP) * 2;
#pragma unroll
    for (int c = 0; c < 4; c++)
        LDSM4(qf[c][0], qf[c][1], qf[c][2], qf[c][3],
              qaddr + (16 * c + (lane >> 4) * 8) * 2);

    float m0 = -1e30f, m1 = -1e30f, l0 = 0.f, l1 = 0.f;
    float o[8][4];
#pragma unroll
    for (int j = 0; j < 8; j++)
#pragma unroll
        for (int r = 0; r < 4; r++) o[j][r] = 0.f;

    for (int kt = 0; kt < NCHUNK; kt++) {
        int s = kt & 1;
        uint4 nk[2], nv[2];
        bool more = (kt + 1 < NCHUNK);
        if (more) {
            int kc = (kt + 1) * 64 + krow;
            bool ok = kc < NR;
            const uint4* ks = (const uint4*)(Kg + (size_t)(ok ? kc : 0) * DHH + kq * 16);
            const uint4* vs = (const uint4*)(Vg + (size_t)(ok ? kc : 0) * CC + kq * 16);
            nk[0] = ok ? ks[0] : z4; nk[1] = ok ? ks[1] : z4;
            nv[0] = ok ? vs[0] : z4; nv[1] = ok ? vs[1] : z4;
        }

        uint32_t kb = s2u(&Ks[s * 64 * FAP]);
        uint32_t vb = s2u(&Vs[s * 64 * FAP]);

        float sc[8][4];
#pragma unroll
        for (int j = 0; j < 8; j++) {
            sc[j][0] = sc[j][1] = sc[j][2] = sc[j][3] = 0.f;
#pragma unroll
            for (int c = 0; c < 4; c++) {
                uint32_t b0, b1;
                LDSM2(b0, b1, kb + ((8 * j + (lane & 7)) * FAP +
                                    16 * c + ((lane >> 3) & 1) * 8) * 2);
                MMA16816(sc[j][0], sc[j][1], sc[j][2], sc[j][3],
                         qf[c][0], qf[c][1], qf[c][2], qf[c][3], b0, b1);
            }
        }

        if (kt * 64 + 64 > NR) {
#pragma unroll
            for (int j = 0; j < 8; j++) {
                int col = kt * 64 + 8 * j + 2 * (lane & 3);
                if (col >= NR)     { sc[j][0] = -1e30f; sc[j][2] = -1e30f; }
                if (col + 1 >= NR) { sc[j][1] = -1e30f; sc[j][3] = -1e30f; }
            }
        }

        float rm0 = -1e30f, rm1 = -1e30f;
#pragma unroll
        for (int j = 0; j < 8; j++) {
            rm0 = fmaxf(rm0, fmaxf(sc[j][0], sc[j][1]));
            rm1 = fmaxf(rm1, fmaxf(sc[j][2], sc[j][3]));
        }
        rm0 = fmaxf(rm0, __shfl_xor_sync(0xffffffffu, rm0, 1));
        rm0 = fmaxf(rm0, __shfl_xor_sync(0xffffffffu, rm0, 2));
        rm1 = fmaxf(rm1, __shfl_xor_sync(0xffffffffu, rm1, 1));
        rm1 = fmaxf(rm1, __shfl_xor_sync(0xffffffffu, rm1, 2));
        float mn0 = fmaxf(m0, rm0), mn1 = fmaxf(m1, rm1);
        float cr0 = __expf(m0 - mn0), cr1 = __expf(m1 - mn1);
        m0 = mn0; m1 = mn1;
        float s0 = 0.f, s1 = 0.f;
#pragma unroll
        for (int j = 0; j < 8; j++) {
            sc[j][0] = __expf(sc[j][0] - mn0);
            sc[j][1] = __expf(sc[j][1] - mn0);
            sc[j][2] = __expf(sc[j][2] - mn1);
            sc[j][3] = __expf(sc[j][3] - mn1);
            s0 += sc[j][0] + sc[j][1];
            s1 += sc[j][2] + sc[j][3];
        }
        s0 += __shfl_xor_sync(0xffffffffu, s0, 1);
        s0 += __shfl_xor_sync(0xffffffffu, s0, 2);
        s1 += __shfl_xor_sync(0xffffffffu, s1, 1);
        s1 += __shfl_xor_sync(0xffffffffu, s1, 2);
        l0 = l0 * cr0 + s0;
        l1 = l1 * cr1 + s1;
#pragma unroll
        for (int j = 0; j < 8; j++) {
            o[j][0] *= cr0; o[j][1] *= cr0;
            o[j][2] *= cr1; o[j][3] *= cr1;
        }

        uint32_t pa[4][4];
#pragma unroll
        for (int c = 0; c < 4; c++) {
            pa[c][0] = packh(sc[2 * c][0], sc[2 * c][1]);
            pa[c][1] = packh(sc[2 * c][2], sc[2 * c][3]);
            pa[c][2] = packh(sc[2 * c + 1][0], sc[2 * c + 1][1]);
            pa[c][3] = packh(sc[2 * c + 1][2], sc[2 * c + 1][3]);
        }

#pragma unroll
        for (int j = 0; j < 8; j++) {
#pragma unroll
            for (int c = 0; c < 4; c++) {
                uint32_t b0, b1;
                LDSM2T(b0, b1, vb + ((16 * c + (lane & 15)) * FAP + 8 * j) * 2);
                MMA16816(o[j][0], o[j][1], o[j][2], o[j][3],
                         pa[c][0], pa[c][1], pa[c][2], pa[c][3], b0, b1);
            }
        }

        if (more) {
            int d = s ^ 1;
            uint4* kd = (uint4*)&Ks[d * 64 * FAP + krow * FAP + kq * 16];
            uint4* vd = (uint4*)&Vs[d * 64 * FAP + krow * FAP + kq * 16];
            kd[0] = nk[0]; kd[1] = nk[1];
            vd[0] = nv[0]; vd[1] = nv[1];
        }
        __syncthreads();
    }

    int r0 = qbase + wid * 16 + (lane >> 2);
    float inv0 = 1.f / l0, inv1 = 1.f / l1;
#pragma unroll
    for (int j = 0; j < 8; j++) {
        int col = h * 64 + 8 * j + 2 * (lane & 3);
#pragma unroll
        for (int half = 0; half < 2; half++) {
            int r = r0 + half * 8;
            if (r >= NR) continue;
            float va = o[j][2 * half + 0] * (half ? inv1 : inv0);
            float vbv = o[j][2 * half + 1] * (half ? inv1 : inv0);
            *(__half2*)&g_ao[((size_t)b * NR + r) * GK + col] =
                __floats2half2_rn(va, vbv);
        }
    }
}

// ------------------------- stage 7: residual + upsample (dense) ------------
__global__ void k_out1(const float* __restrict__ x, const float* __restrict__ cached,
                       float* __restrict__ out) {
    size_t e = ((size_t)blockIdx.x * 256 + threadIdx.x) * 4;
    int b = (int)(e >> 22);
    int rem = (int)(e & ((1u << 22) - 1));
    int l = rem >> 10, c = rem & 1023;
    int hh = l >> 6, ww = l & 63;
    size_t uoff = ((((size_t)b * 32 + (hh >> 1)) * 32) + (ww >> 1)) * 1024 + c;
    float4 xv = *(const float4*)(x + e);
    float4 uv = *(const float4*)(cached + uoff);
    *(float4*)(out + e) = make_float4(xv.x + uv.x, xv.y + uv.y, xv.z + uv.z, xv.w + uv.w);
}

// ------------------------- launcher ----------------------------------------
extern "C" void kernel_launch(void* const* d_in, const int* in_sizes, int n_in,
                              void* d_out, int out_size) {
    const float* x      = (const float*)d_in[0];
    const float* cached = (const float*)d_in[1];
    const float* Wqkv   = (const float*)d_in[2];
    const float* qb     = (const float*)d_in[3];
    const float* vb     = (const float*)d_in[4];
    const float* Wproj  = (const float*)d_in[5];
    const float* bp     = (const float*)d_in[6];
    const float* slog   = (const float*)d_in[7];
    const float* rope   = (const float*)d_in[8];
    float* out = (float*)d_out;

    void *p_qkvh, *p_bias, *p_ax, *p_wq, *p_wp, *p_ao;
    cudaGetSymbolAddress(&p_qkvh, g_qkvh);
    cudaGetSymbolAddress(&p_bias, g_bias);
    cudaGetSymbolAddress(&p_ax, g_ax);
    cudaGetSymbolAddress(&p_wq, g_wq);
    cudaGetSymbolAddress(&p_wp, g_wp);
    cudaGetSymbolAddress(&p_ao, g_ao);

    cudaFuncSetAttribute(k_fattn, cudaFuncAttributeMaxDynamicSharedMemorySize, FA_SMEM);

    k_colsum<<<dim3(4, 8, BB), 256>>>(x);
    k_meanfin<<<8, 256>>>();
    k_mse<<<dim3(LL, BB), 256>>>(x);
    k_topk<<<BB, 1024>>>();
    k_bias<<<12, 256>>>(qb, vb);

    // pack fp16 operands
    k_packW<<<(QKVW * CC / 4 + 255) / 256, 256>>>(Wqkv, (__half*)p_wq, QKVW * CC);
    k_packW<<<(CC * CC / 4 + 255) / 256, 256>>>(Wproj, (__half*)p_wp, CC * CC);
    k_packAx<<<(BB * NR * CC / 4 + 255) / 256, 256>>>(x, (__half*)p_ax);

    // QKV projection: fp16 output
    k_mgemm<0><<<dim3(QKVW / 128, (NR + 63) / 64, BB), 256>>>(
        (const __half*)p_ax, (const __half*)p_wq, (const float*)p_bias,
        (__half*)p_qkvh, nullptr, nullptr,
        NR, QKVW, (size_t)NR * GK, (size_t)NR * QKVW);

    k_qkprep<<<dim3(NR, BB), 512>>>(rope, slog);

    // dense residual+upsample BEFORE the fused proj scatter
    k_out1<<<8192, 256>>>(x, cached, out);

    // tensor-core flash attention (writes proj A operand directly)
    k_fattn<<<dim3((NR + 127) / 128, NHH, BB), 256, FA_SMEM>>>();

    // output projection fused with residual scatter (overwrites selected rows)
    k_mgemm<1><<<dim3(CC / 128, (NR + 63) / 64, BB), 256>>>(
        (const __half*)p_ao, (const __half*)p_wp, bp,
        nullptr, out, x,
        NR, CC, (size_t)NR * GK, 0);
}

// round 14
// speedup vs baseline: 1.0906x; 1.0906x over previous
#include <cuda_runtime.h>
#include <cuda_fp16.h>
#include <math.h>
#include <stdint.h>

#define BB 2
#define LL 4096
#define CC 1024
#define NHH 16
#define DHH 64
#define NR 1638
#define QKVW 3072
#define GK 1024

// ------------------------- scratch (device globals; no runtime alloc) -------
__device__ float g_mean[BB * CC];
__device__ double g_part[BB * 8 * CC];
__device__ float g_mse[BB * LL];
__device__ int g_idx[BB * NR];
__device__ float g_bias[QKVW];
__device__ __half g_qkvh[(size_t)BB * NR * QKVW];  // (b, i, 3*C) fp16
// fp16 attention operands
__device__ __half g_qh[(size_t)BB * NHH * NR * DHH];
__device__ __half g_kh[(size_t)BB * NHH * NR * DHH];
__device__ __half g_vh[(size_t)BB * NR * CC];
// fp16 GEMM operands
__device__ __half g_ax[(size_t)BB * NR * GK];   // x[idx] fp16
__device__ __half g_wq[(size_t)QKVW * GK];      // Wqkv fp16
__device__ __half g_wp[(size_t)CC * GK];        // Wproj fp16
__device__ __half g_ao[(size_t)BB * NR * GK];   // attn out fp16 (written by fattn)

// ------------------------- helpers -----------------------------------------
__device__ __forceinline__ float warpSumF(float v) {
#pragma unroll
    for (int m = 16; m; m >>= 1) v += __shfl_xor_sync(0xffffffffu, v, m);
    return v;
}
__device__ __forceinline__ double warpSumD(double v) {
#pragma unroll
    for (int m = 16; m; m >>= 1) v += __shfl_xor_sync(0xffffffffu, v, m);
    return v;
}
__device__ __forceinline__ uint32_t s2u(const void* p) {
    uint32_t a;
    asm("{ .reg .u64 t; cvta.to.shared.u64 t, %1; cvt.u32.u64 %0, t; }" : "=r"(a) : "l"(p));
    return a;
}
__device__ __forceinline__ uint32_t packh(float a, float b) {
    __half2 t = __floats2half2_rn(a, b);
    return *(uint32_t*)&t;
}
#define LDSM4(d0, d1, d2, d3, addr) \
    asm volatile("ldmatrix.sync.aligned.m8n8.x4.shared.b16 {%0,%1,%2,%3}, [%4];" \
                 : "=r"(d0), "=r"(d1), "=r"(d2), "=r"(d3) : "r"(addr))
#define LDSM2(d0, d1, addr) \
    asm volatile("ldmatrix.sync.aligned.m8n8.x2.shared.b16 {%0,%1}, [%2];" \
                 : "=r"(d0), "=r"(d1) : "r"(addr))
#define LDSM2T(d0, d1, addr) \
    asm volatile("ldmatrix.sync.aligned.m8n8.x2.trans.shared.b16 {%0,%1}, [%2];" \
                 : "=r"(d0), "=r"(d1) : "r"(addr))
#define MMA16816(c0, c1, c2, c3, a0, a1, a2, a3, b0, b1) \
    asm volatile("mma.sync.aligned.m16n8k16.row.col.f32.f16.f16.f32 " \
                 "{%0,%1,%2,%3}, {%4,%5,%6,%7}, {%8,%9}, {%0,%1,%2,%3};" \
                 : "+f"(c0), "+f"(c1), "+f"(c2), "+f"(c3) \
                 : "r"(a0), "r"(a1), "r"(a2), "r"(a3), "r"(b0), "r"(b1))

// ------------------------- stage 1: mean over L (fp64 accum) ---------------
__global__ void k_colsum(const float* __restrict__ x) {
    int c = blockIdx.x * 256 + threadIdx.x;
    int b = blockIdx.z;
    int l0 = blockIdx.y * 512;
    const float* p = x + ((size_t)b * LL + l0) * CC + c;
    double a0 = 0, a1 = 0, a2 = 0, a3 = 0;
#pragma unroll 4
    for (int l = 0; l < 512; l += 4) {
        a0 += (double)p[(size_t)(l + 0) * CC];
        a1 += (double)p[(size_t)(l + 1) * CC];
        a2 += (double)p[(size_t)(l + 2) * CC];
        a3 += (double)p[(size_t)(l + 3) * CC];
    }
    g_part[(b * 8 + blockIdx.y) * CC + c] = a0 + a1 + a2 + a3;
}

__global__ void k_meanfin() {
    int i = blockIdx.x * 256 + threadIdx.x;
    int b = i >> 10, c = i & 1023;
    double s = 0;
#pragma unroll
    for (int k = 0; k < 8; k++) s += g_part[(b * 8 + k) * CC + c];
    g_mean[b * CC + c] = (float)(s * (1.0 / (double)LL));
}

// ------------------------- stage 2: per-row mse (fp64 accum) ---------------
__global__ void k_mse(const float* __restrict__ x) {
    int l = blockIdx.x, b = blockIdx.y;
    const float* xr = x + ((size_t)b * LL + l) * CC;
    double acc = 0;
#pragma unroll
    for (int k = 0; k < 4; k++) {
        int c = threadIdx.x + k * 256;
        double d = (double)xr[c] - (double)g_mean[b * CC + c];
        acc += d * d;
    }
    acc = warpSumD(acc);
    __shared__ double red[8];
    if ((threadIdx.x & 31) == 0) red[threadIdx.x >> 5] = acc;
    __syncthreads();
    if (threadIdx.x == 0) {
        double t = 0;
#pragma unroll
        for (int w = 0; w < 8; w++) t += red[w];
        g_mse[b * LL + l] = (float)t;
    }
}

// ------------------------- stage 3: top-NR radix select (parallel scan) ----
__global__ void k_topk() {
    __shared__ unsigned int hist[256];
    __shared__ unsigned int suf[256];
    __shared__ unsigned int sh_pref, sh_rank, sh_cgt, sh_ceq;
    int b = blockIdx.x, tid = threadIdx.x;
    unsigned int key[4];
#pragma unroll
    for (int k = 0; k < 4; k++)
        key[k] = __float_as_uint(g_mse[b * LL + tid * 4 + k]);
    if (tid == 0) { sh_pref = 0; sh_rank = NR; }
#pragma unroll
    for (int pass = 0; pass < 4; pass++) {
        int shift = 24 - pass * 8;
        if (tid < 256) hist[tid] = 0;
        __syncthreads();
        unsigned int pref = sh_pref, r = sh_rank;
        unsigned int himask = (pass == 0) ? 0u : (0xFFFFFFFFu << (shift + 8));
#pragma unroll
        for (int k = 0; k < 4; k++)
            if ((key[k] & himask) == pref)
                atomicAdd(&hist[(key[k] >> shift) & 255], 1u);
        __syncthreads();
        if (tid < 256) suf[tid] = hist[tid];
        __syncthreads();
#pragma unroll
        for (int off = 1; off < 256; off <<= 1) {
            unsigned int t = 0;
            if (tid < 256 && tid + off < 256) t = suf[tid + off];
            __syncthreads();
            if (tid < 256) suf[tid] += t;
            __syncthreads();
        }
        if (tid < 256) {
            unsigned int hi = (tid == 255) ? 0u : suf[tid + 1];
            if (suf[tid] >= r && hi < r) {
                sh_pref = pref | ((unsigned int)tid << shift);
                sh_rank = r - hi;
            }
        }
        __syncthreads();
    }
    if (tid == 0) { sh_cgt = 0; sh_ceq = 0; }
    __syncthreads();
    unsigned int thr = sh_pref, need = sh_rank;
    int ngt = NR - (int)need;
#pragma unroll
    for (int k = 0; k < 4; k++) {
        if (key[k] > thr) {
            unsigned int p = atomicAdd(&sh_cgt, 1u);
            g_idx[b * NR + p] = tid * 4 + k;
        } else if (key[k] == thr) {
            unsigned int p = atomicAdd(&sh_ceq, 1u);
            if (p < need) g_idx[b * NR + ngt + p] = tid * 4 + k;
        }
    }
}

// ------------------------- stage 4: fused bias ------------------------------
__global__ void k_bias(const float* __restrict__ qb, const float* __restrict__ vb) {
    int i = blockIdx.x * 256 + threadIdx.x;
    if (i < QKVW) g_bias[i] = (i < CC) ? qb[i] : ((i < 2 * CC) ? 0.f : vb[i - 2 * CC]);
}

// ------------------------- pack kernels (fp32 -> fp16) ----------------------
__global__ void k_packW(const float* __restrict__ W, __half* __restrict__ out, int total) {
    int i = (blockIdx.x * 256 + threadIdx.x) * 4;
    if (i >= total) return;
    float4 v = *(const float4*)(W + i);
    *(__half2*)(out + i) = __floats2half2_rn(v.x, v.y);
    *(__half2*)(out + i + 2) = __floats2half2_rn(v.z, v.w);
}
__global__ void k_packAx(const float* __restrict__ x, __half* __restrict__ out) {
    int i = (blockIdx.x * 256 + threadIdx.x) * 4;
    if (i >= BB * NR * CC) return;
    int c = i & 1023;
    int t = i >> 10;
    int r = t % NR, b = t / NR;
    int li = g_idx[b * NR + r];
    float4 v = *(const float4*)(x + ((size_t)b * LL + li) * CC + c);
    *(__half2*)(out + i) = __floats2half2_rn(v.x, v.y);
    *(__half2*)(out + i + 2) = __floats2half2_rn(v.z, v.w);
}

// ------------------------- tensor GEMM via mma.sync fp16 -------------------
// BM=128 BN=128 BK=32, 8 warps (2x4), warp tile 64x32  (R10-proven shape).
// MODE 0: C = A@B^T + bias -> fp16 Ch (batched by cBatch).
// MODE 1: out[(b,idx[r])] = x[(b,idx[r])] + A@B^T + bias  (fused proj+scatter)
#define PITCH 40
#define KITERS (GK / 32)   // 32

template <int MODE>
__global__ void __launch_bounds__(256, 2) k_mgemm(
    const __half* __restrict__ A, const __half* __restrict__ Bm,
    const float* __restrict__ bias,
    __half* __restrict__ Ch, float* __restrict__ outp, const float* __restrict__ xres,
    int M, int N, size_t aBatch, size_t cBatch)
{
    __shared__ __half Asm[2][128 * PITCH];
    __shared__ __half Bsm[2][128 * PITCH];

    int tid = threadIdx.x, wid = tid >> 5, lane = tid & 31;
    int bm = blockIdx.y * 128, bn = blockIdx.x * 128, b = blockIdx.z;
    int wm = wid >> 2, wn = wid & 3;
    const __half* Ab = A + (size_t)b * aBatch;

    int lr = tid >> 1, lc = (tid & 1) * 16;
    bool aok = (bm + lr < M);
    const uint4* aG = (const uint4*)(Ab + (size_t)(aok ? bm + lr : 0) * GK + lc);
    const uint4* bG = (const uint4*)(Bm + (size_t)(bn + lr) * GK + lc);
    const uint32_t BUF = 128 * PITCH * 2;
    const uint4 z4 = make_uint4(0, 0, 0, 0);

    uint32_t aL = s2u(&Asm[0][0]) +
                  ((wm * 64 + (lane & 15)) * PITCH + (lane >> 4) * 8) * 2;
    uint32_t bL = s2u(&Bsm[0][0]) +
                  ((wn * 32 + (lane & 7)) * PITCH + ((lane >> 3) & 1) * 8) * 2;

    float acc[4][4][4];
#pragma unroll
    for (int i = 0; i < 4; i++)
#pragma unroll
        for (int j = 0; j < 4; j++)
#pragma unroll
            for (int r = 0; r < 4; r++) acc[i][j][r] = 0.f;

    {
        uint4 a0 = aok ? aG[0] : z4;
        uint4 a1 = aok ? aG[1] : z4;
        uint4 b0 = bG[0], b1 = bG[1];
        *(uint4*)(Asm[0] + lr * PITCH + lc) = a0;
        *(uint4*)(Asm[0] + lr * PITCH + lc + 8) = a1;
        *(uint4*)(Bsm[0] + lr * PITCH + lc) = b0;
        *(uint4*)(Bsm[0] + lr * PITCH + lc + 8) = b1;
    }
    __syncthreads();

    for (int kt = 0; kt < KITERS; kt++) {
        int s = kt & 1;
        uint4 na0, na1, nb0, nb1;
        bool more = (kt + 1 < KITERS);
        if (more) {
            const uint4* ag = (const uint4*)((const __half*)aG + (kt + 1) * 32);
            const uint4* bg = (const uint4*)((const __half*)bG + (kt + 1) * 32);
            na0 = aok ? ag[0] : z4;
            na1 = aok ? ag[1] : z4;
            nb0 = bg[0]; nb1 = bg[1];
        }

        uint32_t aBase = aL + s * BUF, bBase = bL + s * BUF;
#pragma unroll
        for (int k16 = 0; k16 < 2; k16++) {
            uint32_t af[4][4], bf[4][2];
#pragma unroll
            for (int i = 0; i < 4; i++)
                LDSM4(af[i][0], af[i][1], af[i][2], af[i][3],
                      aBase + (i * 16 * PITCH + k16 * 16) * 2);
#pragma unroll
            for (int j = 0; j < 4; j++)
                LDSM2(bf[j][0], bf[j][1],
                      bBase + (j * 8 * PITCH + k16 * 16) * 2);
#pragma unroll
            for (int i = 0; i < 4; i++)
#pragma unroll
                for (int j = 0; j < 4; j++)
                    MMA16816(acc[i][j][0], acc[i][j][1], acc[i][j][2], acc[i][j][3],
                             af[i][0], af[i][1], af[i][2], af[i][3],
                             bf[j][0], bf[j][1]);
        }

        if (more) {
            int d = s ^ 1;
            *(uint4*)((char*)(Asm[0] + lr * PITCH + lc) + d * BUF) = na0;
            *(uint4*)((char*)(Asm[0] + lr * PITCH + lc + 8) + d * BUF) = na1;
            *(uint4*)((char*)(Bsm[0] + lr * PITCH + lc) + d * BUF) = nb0;
            *(uint4*)((char*)(Bsm[0] + lr * PITCH + lc + 8) + d * BUF) = nb1;
        }
        __syncthreads();
    }

    int rq = lane >> 2, cq = (lane & 3) * 2;
    if (MODE == 0) {
        __half* Cb = Ch + (size_t)b * cBatch;
#pragma unroll
        for (int i = 0; i < 4; i++) {
#pragma unroll
            for (int hh = 0; hh < 2; hh++) {
                int r = bm + wm * 64 + i * 16 + rq + hh * 8;
                if (r >= M) continue;
#pragma unroll
                for (int j = 0; j < 4; j++) {
                    int col = bn + wn * 32 + j * 8 + cq;
                    float a0 = acc[i][j][hh * 2 + 0] + bias[col];
                    float a1 = acc[i][j][hh * 2 + 1] + bias[col + 1];
                    *(__half2*)(Cb + (size_t)r * N + col) = __floats2half2_rn(a0, a1);
                }
            }
        }
    } else {
#pragma unroll
        for (int i = 0; i < 4; i++) {
#pragma unroll
            for (int hh = 0; hh < 2; hh++) {
                int r = bm + wm * 64 + i * 16 + rq + hh * 8;
                if (r >= M) continue;
                int li = g_idx[b * NR + r];
                size_t rowoff = ((size_t)b * LL + li) * CC;
#pragma unroll
                for (int j = 0; j < 4; j++) {
                    int col = bn + wn * 32 + j * 8 + cq;
                    float a0 = acc[i][j][hh * 2 + 0] + bias[col];
                    float a1 = acc[i][j][hh * 2 + 1] + bias[col + 1];
                    float2 xv = *(const float2*)(xres + rowoff + col);
                    *(float2*)(outp + rowoff + col) = make_float2(a0 + xv.x, a1 + xv.y);
                }
            }
        }
    }
}

// ------------------------- stage 5: l2norm + scale + rope (-> fp16) --------
__global__ void k_qkprep(const float* __restrict__ rope, const float* __restrict__ slog) {
    int i = blockIdx.x, b = blockIdx.y;
    int h = threadIdx.x >> 5, p = threadIdx.x & 31;
    int li = g_idx[b * NR + i];
    const __half* base = g_qkvh + ((size_t)b * NR + i) * QKVW;
    float2 q = __half22float2(*(const __half2*)(base + h * 64 + 2 * p));
    float2 kk = __half22float2(*(const __half2*)(base + CC + h * 64 + 2 * p));
    __half2 vh = *(const __half2*)(base + 2 * CC + h * 64 + 2 * p);
    float nq = warpSumF(q.x * q.x + q.y * q.y);
    float nk = warpSumF(kk.x * kk.x + kk.y * kk.y);
    float sm = __expf(fminf(slog[h], 4.6051701859880914f));
    float qs = sm / fmaxf(sqrtf(nq), 1e-12f);
    float ks = 1.f / fmaxf(sqrtf(nk), 1e-12f);
    float cv = rope[(size_t)li * 32 + p];
    float sv = rope[(size_t)LL * 32 + (size_t)li * 32 + p];
    float q0 = q.x * qs, q1 = q.y * qs;
    float k0 = kk.x * ks, k1 = kk.y * ks;
    size_t off = (((size_t)b * NHH + h) * NR + i) * DHH + 2 * p;
    *(__half2*)(g_qh + off) = __floats2half2_rn(cv * q0 - sv * q1, sv * q0 + cv * q1);
    *(__half2*)(g_kh + off) = __floats2half2_rn(cv * k0 - sv * k1, sv * k0 + cv * k1);
    *(__half2*)(g_vh + ((size_t)b * NR + i) * CC + h * 64 + 2 * p) = vh;
}

// ------------------------- stage 6: tensor-core flash attention ------------
#define FAP 72
#define NCHUNK 26
#define FA_SMEM ((128 * FAP + 4 * 64 * FAP) * 2)

__global__ void __launch_bounds__(256, 2) k_fattn() {
    extern __shared__ __half fsm[];
    __half* Qs = fsm;
    __half* Ks = Qs + 128 * FAP;
    __half* Vs = Ks + 2 * 64 * FAP;
    int tid = threadIdx.x, wid = tid >> 5, lane = tid & 31;
    int qbase = blockIdx.x * 128;
    int h = blockIdx.y, b = blockIdx.z;
    const __half* Qg = g_qh + ((size_t)(b * NHH + h)) * NR * DHH;
    const __half* Kg = g_kh + ((size_t)(b * NHH + h)) * NR * DHH;
    const __half* Vg = g_vh + (size_t)b * NR * CC + h * 64;

    const uint4 z4 = make_uint4(0, 0, 0, 0);
    int lrow = tid >> 1, lhalf = tid & 1;
    int krow = tid >> 2, kq = tid & 3;

    {   // Q tile
        int qi = qbase + lrow;
        const uint4* src = (const uint4*)(Qg + (size_t)(qi < NR ? qi : 0) * DHH + lhalf * 32);
        uint4* dst = (uint4*)&Qs[lrow * FAP + lhalf * 32];
#pragma unroll
        for (int t = 0; t < 4; t++) dst[t] = (qi < NR) ? src[t] : z4;
    }
    {   // K/V chunk 0
        const uint4* ks = (const uint4*)(Kg + (size_t)krow * DHH + kq * 16);
        const uint4* vs = (const uint4*)(Vg + (size_t)krow * CC + kq * 16);
        uint4* kd = (uint4*)&Ks[krow * FAP + kq * 16];
        uint4* vd = (uint4*)&Vs[krow * FAP + kq * 16];
        kd[0] = ks[0]; kd[1] = ks[1];
        vd[0] = vs[0]; vd[1] = vs[1];
    }
    __syncthreads();

    uint32_t qf[4][4];
    uint32_t qaddr = s2u(Qs) + ((wid * 16 + (lane & 15)) * FAP) * 2;
#pragma unroll
    for (int c = 0; c < 4; c++)
        LDSM4(qf[c][0], qf[c][1], qf[c][2], qf[c][3],
              qaddr + (16 * c + (lane >> 4) * 8) * 2);

    float m0 = -1e30f, m1 = -1e30f, l0 = 0.f, l1 = 0.f;
    float o[8][4];
#pragma unroll
    for (int j = 0; j < 8; j++)
#pragma unroll
        for (int r = 0; r < 4; r++) o[j][r] = 0.f;

    for (int kt = 0; kt < NCHUNK; kt++) {
        int s = kt & 1;
        uint4 nk[2], nv[2];
        bool more = (kt + 1 < NCHUNK);
        if (more) {
            int kc = (kt + 1) * 64 + krow;
            bool ok = kc < NR;
            const uint4* ks = (const uint4*)(Kg + (size_t)(ok ? kc : 0) * DHH + kq * 16);
            const uint4* vs = (const uint4*)(Vg + (size_t)(ok ? kc : 0) * CC + kq * 16);
            nk[0] = ok ? ks[0] : z4; nk[1] = ok ? ks[1] : z4;
            nv[0] = ok ? vs[0] : z4; nv[1] = ok ? vs[1] : z4;
        }

        uint32_t kb = s2u(&Ks[s * 64 * FAP]);
        uint32_t vb = s2u(&Vs[s * 64 * FAP]);

        float sc[8][4];
#pragma unroll
        for (int j = 0; j < 8; j++) {
            sc[j][0] = sc[j][1] = sc[j][2] = sc[j][3] = 0.f;
#pragma unroll
            for (int c = 0; c < 4; c++) {
                uint32_t b0, b1;
                LDSM2(b0, b1, kb + ((8 * j + (lane & 7)) * FAP +
                                    16 * c + ((lane >> 3) & 1) * 8) * 2);
                MMA16816(sc[j][0], sc[j][1], sc[j][2], sc[j][3],
                         qf[c][0], qf[c][1], qf[c][2], qf[c][3], b0, b1);
            }
        }

        if (kt * 64 + 64 > NR) {
#pragma unroll
            for (int j = 0; j < 8; j++) {
                int col = kt * 64 + 8 * j + 2 * (lane & 3);
                if (col >= NR)     { sc[j][0] = -1e30f; sc[j][2] = -1e30f; }
                if (col + 1 >= NR) { sc[j][1] = -1e30f; sc[j][3] = -1e30f; }
            }
        }

        float rm0 = -1e30f, rm1 = -1e30f;
#pragma unroll
        for (int j = 0; j < 8; j++) {
            rm0 = fmaxf(rm0, fmaxf(sc[j][0], sc[j][1]));
            rm1 = fmaxf(rm1, fmaxf(sc[j][2], sc[j][3]));
        }
        rm0 = fmaxf(rm0, __shfl_xor_sync(0xffffffffu, rm0, 1));
        rm0 = fmaxf(rm0, __shfl_xor_sync(0xffffffffu, rm0, 2));
        rm1 = fmaxf(rm1, __shfl_xor_sync(0xffffffffu, rm1, 1));
        rm1 = fmaxf(rm1, __shfl_xor_sync(0xffffffffu, rm1, 2));
        float mn0 = fmaxf(m0, rm0), mn1 = fmaxf(m1, rm1);
        float cr0 = __expf(m0 - mn0), cr1 = __expf(m1 - mn1);
        m0 = mn0; m1 = mn1;
        float s0 = 0.f, s1 = 0.f;
#pragma unroll
        for (int j = 0; j < 8; j++) {
            sc[j][0] = __expf(sc[j][0] - mn0);
            sc[j][1] = __expf(sc[j][1] - mn0);
            sc[j][2] = __expf(sc[j][2] - mn1);
            sc[j][3] = __expf(sc[j][3] - mn1);
            s0 += sc[j][0] + sc[j][1];
            s1 += sc[j][2] + sc[j][3];
        }
        s0 += __shfl_xor_sync(0xffffffffu, s0, 1);
        s0 += __shfl_xor_sync(0xffffffffu, s0, 2);
        s1 += __shfl_xor_sync(0xffffffffu, s1, 1);
        s1 += __shfl_xor_sync(0xffffffffu, s1, 2);
        l0 = l0 * cr0 + s0;
        l1 = l1 * cr1 + s1;
#pragma unroll
        for (int j = 0; j < 8; j++) {
            o[j][0] *= cr0; o[j][1] *= cr0;
            o[j][2] *= cr1; o[j][3] *= cr1;
        }

        uint32_t pa[4][4];
#pragma unroll
        for (int c = 0; c < 4; c++) {
            pa[c][0] = packh(sc[2 * c][0], sc[2 * c][1]);
            pa[c][1] = packh(sc[2 * c][2], sc[2 * c][3]);
            pa[c][2] = packh(sc[2 * c + 1][0], sc[2 * c + 1][1]);
            pa[c][3] = packh(sc[2 * c + 1][2], sc[2 * c + 1][3]);
        }

#pragma unroll
        for (int j = 0; j < 8; j++) {
#pragma unroll
            for (int c = 0; c < 4; c++) {
                uint32_t b0, b1;
                LDSM2T(b0, b1, vb + ((16 * c + (lane & 15)) * FAP + 8 * j) * 2);
                MMA16816(o[j][0], o[j][1], o[j][2], o[j][3],
                         pa[c][0], pa[c][1], pa[c][2], pa[c][3], b0, b1);
            }
        }

        if (more) {
            int d = s ^ 1;
            uint4* kd = (uint4*)&Ks[d * 64 * FAP + krow * FAP + kq * 16];
            uint4* vd = (uint4*)&Vs[d * 64 * FAP + krow * FAP + kq * 16];
            kd[0] = nk[0]; kd[1] = nk[1];
            vd[0] = nv[0]; vd[1] = nv[1];
        }
        __syncthreads();
    }

    int r0 = qbase + wid * 16 + (lane >> 2);
    float inv0 = 1.f / l0, inv1 = 1.f / l1;
#pragma unroll
    for (int j = 0; j < 8; j++) {
        int col = h * 64 + 8 * j + 2 * (lane & 3);
#pragma unroll
        for (int half = 0; half < 2; half++) {
            int r = r0 + half * 8;
            if (r >= NR) continue;
            float va = o[j][2 * half + 0] * (half ? inv1 : inv0);
            float vbv = o[j][2 * half + 1] * (half ? inv1 : inv0);
            *(__half2*)&g_ao[((size_t)b * NR + r) * GK + col] =
                __floats2half2_rn(va, vbv);
        }
    }
}

// ------------------------- stage 7: residual + upsample (dense) ------------
__global__ void k_out1(const float* __restrict__ x, const float* __restrict__ cached,
                       float* __restrict__ out) {
    size_t e = ((size_t)blockIdx.x * 256 + threadIdx.x) * 4;
    int b = (int)(e >> 22);
    int rem = (int)(e & ((1u << 22) - 1));
    int l = rem >> 10, c = rem & 1023;
    int hh = l >> 6, ww = l & 63;
    size_t uoff = ((((size_t)b * 32 + (hh >> 1)) * 32) + (ww >> 1)) * 1024 + c;
    float4 xv = *(const float4*)(x + e);
    float4 uv = *(const float4*)(cached + uoff);
    *(float4*)(out + e) = make_float4(xv.x + uv.x, xv.y + uv.y, xv.z + uv.z, xv.w + uv.w);
}

// ------------------------- launcher ----------------------------------------
extern "C" void kernel_launch(void* const* d_in, const int* in_sizes, int n_in,
                              void* d_out, int out_size) {
    const float* x      = (const float*)d_in[0];
    const float* cached = (const float*)d_in[1];
    const float* Wqkv   = (const float*)d_in[2];
    const float* qb     = (const float*)d_in[3];
    const float* vb     = (const float*)d_in[4];
    const float* Wproj  = (const float*)d_in[5];
    const float* bp     = (const float*)d_in[6];
    const float* slog   = (const float*)d_in[7];
    const float* rope   = (const float*)d_in[8];
    float* out = (float*)d_out;

    void *p_qkvh, *p_bias, *p_ax, *p_wq, *p_wp, *p_ao;
    cudaGetSymbolAddress(&p_qkvh, g_qkvh);
    cudaGetSymbolAddress(&p_bias, g_bias);
    cudaGetSymbolAddress(&p_ax, g_ax);
    cudaGetSymbolAddress(&p_wq, g_wq);
    cudaGetSymbolAddress(&p_wp, g_wp);
    cudaGetSymbolAddress(&p_ao, g_ao);

    cudaFuncSetAttribute(k_fattn, cudaFuncAttributeMaxDynamicSharedMemorySize, FA_SMEM);

    k_colsum<<<dim3(4, 8, BB), 256>>>(x);
    k_meanfin<<<8, 256>>>();
    k_mse<<<dim3(LL, BB), 256>>>(x);
    k_topk<<<BB, 1024>>>();
    k_bias<<<12, 256>>>(qb, vb);

    // pack fp16 operands
    k_packW<<<(QKVW * CC / 4 + 255) / 256, 256>>>(Wqkv, (__half*)p_wq, QKVW * CC);
    k_packW<<<(CC * CC / 4 + 255) / 256, 256>>>(Wproj, (__half*)p_wp, CC * CC);
    k_packAx<<<(BB * NR * CC / 4 + 255) / 256, 256>>>(x, (__half*)p_ax);

    // QKV projection: fp16 output, BM=128 tiling
    k_mgemm<0><<<dim3(QKVW / 128, (NR + 127) / 128, BB), 256>>>(
        (const __half*)p_ax, (const __half*)p_wq, (const float*)p_bias,
        (__half*)p_qkvh, nullptr, nullptr,
        NR, QKVW, (size_t)NR * GK, (size_t)NR * QKVW);

    k_qkprep<<<dim3(NR, BB), 512>>>(rope, slog);

    // dense residual+upsample BEFORE the fused proj scatter
    k_out1<<<8192, 256>>>(x, cached, out);

    // tensor-core flash attention (writes proj A operand directly)
    k_fattn<<<dim3((NR + 127) / 128, NHH, BB), 256, FA_SMEM>>>();

    // output projection fused with residual scatter (overwrites selected rows)
    k_mgemm<1><<<dim3(CC / 128, (NR + 127) / 128, BB), 256>>>(
        (const __half*)p_ao, (const __half*)p_wp, bp,
        nullptr, out, x,
        NR, CC, (size_t)NR * GK, 0);
}